// round 7
// baseline (speedup 1.0000x reference)
#include <cuda_runtime.h>

// Problem constants
#define BB 8
#define CC 256
#define NN 65536              // 256*256 spatial
#define TILE 32               // pixels per tile
#define TPBATCH 2048          // tiles per batch
#define BPB 38                // blocks per batch (batch-aligned); all even tile counts
#define TPB 54                // ceil(2048/38)
#define GRID_ASSIGN (BB * BPB)  // 304 = 2 blocks/SM * 152 SMs
#define THREADS 256

// Output layout (flat float32 concat of reference returns)
#define OFF_LABELS  512
#define OFF_ONEHOT  (512 + BB * NN)              // 524800
#define OFF_CURDIST (OFF_ONEHOT + 2LL * BB * NN) // 1573376

// -------- device scratch (no allocations allowed) --------
__device__ float g_sums[BB * 2 * CC];   // [b][k][c]
__device__ float g_counts[BB * 2];      // [b][k]
__device__ float g_centers[2 * CC];     // [k][c]
__device__ float g_cn[2 * CC];          // normalized centers, interleaved [c][k]
__device__ unsigned char g_labels[(long long)BB * NN];
__device__ float g_curdist;
__device__ int g_done;

// -------- block reduce of 4 floats (256 threads) --------
__device__ __forceinline__ float4 blockReduce4(float4 v, float* scr) {
#pragma unroll
    for (int o = 16; o > 0; o >>= 1) {
        v.x += __shfl_down_sync(0xffffffffu, v.x, o);
        v.y += __shfl_down_sync(0xffffffffu, v.y, o);
        v.z += __shfl_down_sync(0xffffffffu, v.z, o);
        v.w += __shfl_down_sync(0xffffffffu, v.w, o);
    }
    int wid = threadIdx.x >> 5, lane = threadIdx.x & 31;
    __syncthreads();
    if (lane == 0) {
        scr[wid * 4 + 0] = v.x; scr[wid * 4 + 1] = v.y;
        scr[wid * 4 + 2] = v.z; scr[wid * 4 + 3] = v.w;
    }
    __syncthreads();
    if (threadIdx.x == 0) {
        float a = 0.f, b = 0.f, c = 0.f, d = 0.f;
#pragma unroll
        for (int w = 0; w < 8; w++) {
            a += scr[w * 4 + 0]; b += scr[w * 4 + 1];
            c += scr[w * 4 + 2]; d += scr[w * 4 + 3];
        }
        scr[0] = a; scr[1] = b; scr[2] = c; scr[3] = d;
    }
    __syncthreads();
    return make_float4(scr[0], scr[1], scr[2], scr[3]);
}

// -------- init --------
__global__ void k_init(const float* __restrict__ centerInit) {
    __shared__ float scr[32];
    int c = threadIdx.x;
    float c0 = centerInit[c], c1 = centerInit[CC + c];
    float4 r = blockReduce4(make_float4(c0 * c0, c1 * c1, 0.f, 0.f), scr);
    float n0 = fmaxf(sqrtf(r.x), 1e-12f);
    float n1 = fmaxf(sqrtf(r.y), 1e-12f);
    g_centers[c] = c0; g_centers[CC + c] = c1;
    g_cn[c * 2 + 0] = c0 / n0;
    g_cn[c * 2 + 1] = c1 / n1;
#pragma unroll
    for (int jj = 0; jj < 16; jj++) g_sums[jj * CC + c] = 0.f;
    if (c < 16) g_counts[c] = 0.f;
    if (c == 0) { g_done = 0; g_curdist = 0.f; }
}

// ---- pipelined assign helpers ----
__device__ __forceinline__ void load_tile(float4 v[8], const float* p) {
#pragma unroll
    for (int k = 0; k < 8; k++)
        v[k] = __ldcs((const float4*)(p + (long long)k * (32LL * NN)));
}

// dots + totals + warp pre-reduce (over 4 g-groups in warp) + partial store
__device__ __forceinline__ void dots_store(const float4 v[8], const float2* cn2,
        float accT[8], float* s_part, int g, int j, int poff) {
    float dp[8];
#pragma unroll
    for (int q = 0; q < 8; q++) dp[q] = 0.f;
#pragma unroll
    for (int k = 0; k < 8; k++) {
        float2 w = cn2[g + 32 * k];
        dp[0] = fmaf(v[k].x, w.x, dp[0]); dp[1] = fmaf(v[k].x, w.y, dp[1]);
        dp[2] = fmaf(v[k].y, w.x, dp[2]); dp[3] = fmaf(v[k].y, w.y, dp[3]);
        dp[4] = fmaf(v[k].z, w.x, dp[4]); dp[5] = fmaf(v[k].z, w.y, dp[5]);
        dp[6] = fmaf(v[k].w, w.x, dp[6]); dp[7] = fmaf(v[k].w, w.y, dp[7]);
        accT[k] += (v[k].x + v[k].y) + (v[k].z + v[k].w);
    }
    // pre-reduce over lanes differing in bits 3,4 (same j, different g)
#pragma unroll
    for (int q = 0; q < 8; q++) {
        dp[q] += __shfl_xor_sync(0xffffffffu, dp[q], 8);
        dp[q] += __shfl_xor_sync(0xffffffffu, dp[q], 16);
    }
    if ((threadIdx.x & 31) < 8) {
#pragma unroll
        for (int q = 0; q < 8; q++)
            s_part[poff + ((q + j) & 7)] = dp[q];
    }
}

__device__ __forceinline__ void labels_phase(const float* s_part, float* s_labs,
        int* s_cnt, unsigned char* glab, int tid) {
    if (tid < 64) {
        const int pp = tid >> 1, kk = tid & 1;
        const int jj = pp >> 2, q = (pp & 3) * 2 + kk;
        const int col = 8 * jj + ((q + jj) & 7);
        float s = 0.f;
#pragma unroll
        for (int w = 0; w < 8; w++) s += s_part[w * 72 + col];
        float o = __shfl_xor_sync(0xffffffffu, s, 1);
        int lab = 0;
        if (!kk) {
            lab = (o > s) ? 1 : 0;   // argmin tie -> 0
            s_labs[pp] = (float)lab;
            glab[pp] = (unsigned char)lab;
        }
        unsigned bal = __ballot_sync(0xffffffffu, lab);
        if ((tid & 31) == 0) atomicAdd(s_cnt, __popc(bal));
    }
}

__device__ __forceinline__ void accum_masked(float acc1[8], const float4 v[8],
        const float* s_labs, int j) {
    float4 lb = *(const float4*)(s_labs + 4 * j);
#pragma unroll
    for (int k = 0; k < 8; k++) {
        float a = acc1[k];
        a = fmaf(lb.x, v[k].x, a); a = fmaf(lb.y, v[k].y, a);
        a = fmaf(lb.z, v[k].z, a); a = fmaf(lb.w, v[k].w, a);
        acc1[k] = a;
    }
}

// -------- assign: double-buffered, loads in flight across barriers --------
__global__ void __launch_bounds__(THREADS, 2) k_assign(const float* __restrict__ F) {
    if (g_done) return;  // frozen after convergence
    __shared__ float s_part[8 * 72];    // [warp][8j + rot], pad 72
    __shared__ float s_cn[2 * CC];      // interleaved [c][k]
    __shared__ float s_labs[TILE];
    __shared__ int s_cnt;

    const int tid = threadIdx.x;
    s_cn[tid] = g_cn[tid];
    s_cn[tid + 256] = g_cn[tid + 256];
    if (tid == 0) s_cnt = 0;

    const int batch = blockIdx.x / BPB;
    const int bi = blockIdx.x % BPB;
    const int t0 = bi * TPB;
    int t1 = t0 + TPB; if (t1 > TPBATCH) t1 = TPBATCH;  // counts stay even

    const int g = tid >> 3;   // channels c = g + 32k
    const int j = tid & 7;    // pixels 4j..4j+3
    const int w = tid >> 5;
    const int poff = w * 72 + 8 * j;
    const float* Fb = F + (long long)batch * CC * NN + (long long)g * NN + 4 * j;
    unsigned char* glabB = g_labels + (long long)batch * NN;
    const float2* cn2 = (const float2*)s_cn;

    float acc1[8], accT[8];
#pragma unroll
    for (int k = 0; k < 8; k++) { acc1[k] = 0.f; accT[k] = 0.f; }
    int accCnt = 0;
    __syncthreads();  // s_cn / s_cnt ready

    float4 vA[8], vB[8];
    // prologue
    load_tile(vA, Fb + (long long)t0 * TILE);
    dots_store(vA, cn2, accT, s_part, g, j, poff);

    for (int t = t0; t < t1; t += 2) {
        load_tile(vB, Fb + (long long)(t + 1) * TILE);  // in flight across barriers
        __syncthreads();                                 // partials(t) visible
        labels_phase(s_part, s_labs, &s_cnt, glabB + t * TILE, tid);
        __syncthreads();                                 // labels visible
        if (tid == 0) { accCnt += s_cnt; s_cnt = 0; }    // race-free window
        accum_masked(acc1, vA, s_labs, j);               // consume vA
        dots_store(vB, cn2, accT, s_part, g, j, poff);   // partials(t+1)

        if (t + 2 < t1) load_tile(vA, Fb + (long long)(t + 2) * TILE);
        __syncthreads();                                 // partials(t+1) visible
        labels_phase(s_part, s_labs, &s_cnt, glabB + (t + 1) * TILE, tid);
        __syncthreads();
        if (tid == 0) { accCnt += s_cnt; s_cnt = 0; }
        accum_masked(acc1, vB, s_labs, j);               // consume vB
        if (t + 2 < t1)
            dots_store(vA, cn2, accT, s_part, g, j, poff);  // partials(t+2)
    }

    // ---- flush: reduce across the 8 j-lanes (contiguous in warp) + atomics ----
#pragma unroll
    for (int k = 0; k < 8; k++) {
        float a = acc1[k], s = accT[k];
#pragma unroll
        for (int o = 4; o > 0; o >>= 1) {
            a += __shfl_down_sync(0xffffffffu, a, o, 8);
            s += __shfl_down_sync(0xffffffffu, s, o, 8);
        }
        if (j == 0) {
            int c = g + 32 * k;
            atomicAdd(&g_sums[(batch * 2 + 1) * CC + c], a);
            atomicAdd(&g_sums[(batch * 2 + 0) * CC + c], s - a);
        }
    }
    if (tid == 0) {
        int npix = (t1 - t0) * TILE;
        atomicAdd(&g_counts[batch * 2 + 1], (float)accCnt);
        atomicAdd(&g_counts[batch * 2 + 0], (float)(npix - accCnt));
    }
}

// -------- update: centers_iter, cdist, new centers, done flag --------
__global__ void k_update() {
    if (g_done) return;
    __shared__ float scr[32];
    int c = threadIdx.x;
    float co0 = g_centers[c], co1 = g_centers[CC + c];
    float4 r = blockReduce4(make_float4(co0 * co0, co1 * co1, 0.f, 0.f), scr);
    float no0 = sqrtf(r.x), no1 = sqrtf(r.y);

    float nc0 = 0.f, nc1 = 0.f, cd = 0.f;
#pragma unroll
    for (int b = 0; b < BB; b++) {
        float cnt0 = g_counts[b * 2 + 0] + 1.0f;
        float cnt1 = g_counts[b * 2 + 1] + 1.0f;
        float ci0 = g_sums[(b * 2 + 0) * CC + c] / cnt0;
        float ci1 = g_sums[(b * 2 + 1) * CC + c] / cnt1;
        nc0 += ci0; nc1 += ci1;
        float4 q = blockReduce4(make_float4(ci0 * co0, ci0 * ci0, ci1 * co1, ci1 * ci1), scr);
        float den0 = fmaxf(sqrtf(q.y) * no0, 1e-8f);
        float den1 = fmaxf(sqrtf(q.w) * no1, 1e-8f);
        cd += 0.5f * (q.x / den0 + q.z / den1);
    }
    float cur = cd * 0.125f;
    nc0 *= 0.125f; nc1 *= 0.125f;
    float4 r2 = blockReduce4(make_float4(nc0 * nc0, nc1 * nc1, 0.f, 0.f), scr);
    float nn0 = fmaxf(sqrtf(r2.x), 1e-12f);
    float nn1 = fmaxf(sqrtf(r2.y), 1e-12f);
    g_centers[c] = nc0; g_centers[CC + c] = nc1;
    g_cn[c * 2 + 0] = nc0 / nn0;
    g_cn[c * 2 + 1] = nc1 / nn1;
#pragma unroll
    for (int jj = 0; jj < 16; jj++) g_sums[jj * CC + c] = 0.f;
    if (c < 16) g_counts[c] = 0.f;
    if (c == 0) { g_curdist = cur; if (cur < 0.01f) g_done = 1; }
}

// -------- finalize: write [centers | labels | onehot | cur_dist] --------
__global__ void k_final(float* __restrict__ out, long long outSize) {
    long long i = (long long)blockIdx.x * THREADS + threadIdx.x;
    if (i < 512 && i < outSize) out[i] = g_centers[i];
    if (i < (long long)BB * NN) {
        float lab = (float)g_labels[i];
        long long o1 = OFF_LABELS + i;
        long long o2 = OFF_ONEHOT + 2 * i;
        if (o1 < outSize) out[o1] = lab;
        if (o2 + 1 < outSize) {
            *(float2*)(out + o2) = make_float2(1.0f - lab, lab);
        }
    }
    if (i == 0 && OFF_CURDIST < outSize) out[OFF_CURDIST] = g_curdist;
}

extern "C" void kernel_launch(void* const* d_in, const int* in_sizes, int n_in,
                              void* d_out, int out_size) {
    const float* F = (const float*)d_in[0];
    const float* cinit = (const float*)d_in[1];
    if (n_in >= 2 && in_sizes[0] == 2 * CC) {  // tolerate swapped metadata order
        F = (const float*)d_in[1];
        cinit = (const float*)d_in[0];
    }
    k_init<<<1, THREADS>>>(cinit);
    for (int it = 0; it < 3; it++) {
        k_assign<<<GRID_ASSIGN, THREADS>>>(F);
        k_update<<<1, THREADS>>>();
    }
    k_final<<<(BB * NN) / THREADS, THREADS>>>((float*)d_out, (long long)out_size);
}

// round 8
// speedup vs baseline: 1.0849x; 1.0849x over previous
#include <cuda_runtime.h>

// Problem constants
#define BB 8
#define CC 256
#define NN 65536            // 256*256 spatial
#define TT 64               // pixels per tile
#define TILES_PER_BATCH 1024
#define BLOCKS_PER_BATCH 38 // batch-aligned
#define TPB 27              // ceil(1024/38)
#define GRID_ASSIGN (BB * BLOCKS_PER_BATCH)   // 304 = 2 blocks/SM * 152 SMs
#define THREADS 256

// Output layout (flat float32 concat of reference returns)
#define OFF_LABELS  512
#define OFF_ONEHOT  (512 + BB * NN)              // 524800
#define OFF_CURDIST (OFF_ONEHOT + 2LL * BB * NN) // 1573376

// -------- device scratch (no allocations allowed) --------
__device__ float g_sums[BB * 2 * CC];   // [b][k][c]
__device__ float g_counts[BB * 2];      // [b][k]
__device__ float g_centers[2 * CC];     // [k][c]
__device__ float g_cn[2 * CC];          // normalized centers, interleaved [c][k]
__device__ unsigned char g_labels[(long long)BB * NN];
__device__ float g_curdist;
__device__ int g_done;
__device__ unsigned g_ticket;

// -------- block reduce of 4 floats (256 threads) --------
__device__ __forceinline__ float4 blockReduce4(float4 v, float* scr) {
#pragma unroll
    for (int o = 16; o > 0; o >>= 1) {
        v.x += __shfl_down_sync(0xffffffffu, v.x, o);
        v.y += __shfl_down_sync(0xffffffffu, v.y, o);
        v.z += __shfl_down_sync(0xffffffffu, v.z, o);
        v.w += __shfl_down_sync(0xffffffffu, v.w, o);
    }
    int wid = threadIdx.x >> 5, lane = threadIdx.x & 31;
    __syncthreads();
    if (lane == 0) {
        scr[wid * 4 + 0] = v.x; scr[wid * 4 + 1] = v.y;
        scr[wid * 4 + 2] = v.z; scr[wid * 4 + 3] = v.w;
    }
    __syncthreads();
    if (threadIdx.x == 0) {
        float a = 0.f, b = 0.f, c = 0.f, d = 0.f;
#pragma unroll
        for (int w = 0; w < 8; w++) {
            a += scr[w * 4 + 0]; b += scr[w * 4 + 1];
            c += scr[w * 4 + 2]; d += scr[w * 4 + 3];
        }
        scr[0] = a; scr[1] = b; scr[2] = c; scr[3] = d;
    }
    __syncthreads();
    return make_float4(scr[0], scr[1], scr[2], scr[3]);
}

// -------- init --------
__global__ void k_init(const float* __restrict__ centerInit) {
    __shared__ float scr[32];
    int c = threadIdx.x;
    float c0 = centerInit[c], c1 = centerInit[CC + c];
    float4 r = blockReduce4(make_float4(c0 * c0, c1 * c1, 0.f, 0.f), scr);
    float n0 = fmaxf(sqrtf(r.x), 1e-12f);
    float n1 = fmaxf(sqrtf(r.y), 1e-12f);
    g_centers[c] = c0; g_centers[CC + c] = c1;
    g_cn[c * 2 + 0] = c0 / n0;
    g_cn[c * 2 + 1] = c1 / n1;
#pragma unroll
    for (int jj = 0; jj < 16; jj++) g_sums[jj * CC + c] = 0.f;
    if (c < 16) g_counts[c] = 0.f;
    if (c == 0) { g_done = 0; g_curdist = 0.f; g_ticket = 0u; }
}

// -------- assign (R4 structure) + L2 prefetch + fused last-block update ----
__global__ void __launch_bounds__(THREADS, 2) k_assign(const float* __restrict__ F) {
    if (g_done) return;  // frozen after convergence
    __shared__ float s_part[16 * 129 + 8];  // [g stride 129][8j + (q+j)&7]
    __shared__ float s_cn[2 * CC];          // interleaved [c][k]
    __shared__ float s_labs[TT];
    __shared__ float scr[32];
    __shared__ int s_cnt;
    __shared__ unsigned s_rank;

    const int tid = threadIdx.x;
    s_cn[tid] = g_cn[tid];
    s_cn[tid + 256] = g_cn[tid + 256];
    if (tid == 0) s_cnt = 0;

    const int batch = blockIdx.x / BLOCKS_PER_BATCH;
    const int bi = blockIdx.x % BLOCKS_PER_BATCH;
    const int t0 = bi * TPB;
    int t1 = t0 + TPB; if (t1 > TILES_PER_BATCH) t1 = TILES_PER_BATCH;

    const int g = tid >> 4;      // channel group: channels c = g + 16k
    const int j = tid & 15;      // pixel group: pixels 4j..4j+3
    const float* Fb = F + (long long)batch * CC * NN + (long long)g * NN + 4 * j;
    const float2* cn2 = (const float2*)s_cn;

    float acc1[16], accT[16];
#pragma unroll
    for (int k = 0; k < 16; k++) { acc1[k] = 0.f; accT[k] = 0.f; }
    int accCnt = 0;
    const int poff = 129 * g + 8 * j;
    __syncthreads();  // s_cn / s_cnt ready

    for (int t = t0; t < t1; t++) {
        const float* p = Fb + t * TT;
        // ---- phase 1: streaming loads kept in registers; dots + totals ----
        float4 v[16];
        float dp[8];
#pragma unroll
        for (int q = 0; q < 8; q++) dp[q] = 0.f;
#pragma unroll
        for (int k = 0; k < 16; k++) {
            v[k] = __ldcs((const float4*)(p + (long long)k * (16 * NN)));
            float2 w = cn2[g + 16 * k];
            dp[0] = fmaf(v[k].x, w.x, dp[0]); dp[1] = fmaf(v[k].x, w.y, dp[1]);
            dp[2] = fmaf(v[k].y, w.x, dp[2]); dp[3] = fmaf(v[k].y, w.y, dp[3]);
            dp[4] = fmaf(v[k].z, w.x, dp[4]); dp[5] = fmaf(v[k].z, w.y, dp[5]);
            dp[6] = fmaf(v[k].w, w.x, dp[6]); dp[7] = fmaf(v[k].w, w.y, dp[7]);
            accT[k] += (v[k].x + v[k].y) + (v[k].z + v[k].w);
        }
        // ---- L2 prefetch of next tile (register-free hint) ----
        {
            const float* pn = p + ((t + 1 < t1) ? TT : 0);
#pragma unroll
            for (int k = 0; k < 16; k++)
                asm volatile("prefetch.global.L2 [%0];" ::
                             "l"(pn + (long long)k * (16 * NN)));
        }
        // harvest previous tile's count (ballots completed before last barrier)
        if (tid == 0) { accCnt += s_cnt; s_cnt = 0; }
        // swizzled partial store: conflict-free writes & reads
#pragma unroll
        for (int q = 0; q < 8; q++)
            s_part[poff + ((q + j) & 7)] = dp[q];
        __syncthreads();

        // ---- phase 2: reduce 16 groups -> dots, labels ----
        if (tid < 128) {
            const int off = 8 * (tid >> 3) + (((tid & 7) + (tid >> 3)) & 7);
            float s = 0.f;
#pragma unroll
            for (int gg = 0; gg < 16; gg++) s += s_part[129 * gg + off];
            float o = __shfl_xor_sync(0xffffffffu, s, 1);
            int lab = 0;
            if (!(tid & 1)) {
                lab = (o > s) ? 1 : 0;  // argmin tie -> 0
                int pidx = tid >> 1;
                s_labs[pidx] = (float)lab;
                g_labels[(long long)batch * NN + t * TT + pidx] = (unsigned char)lab;
            }
            unsigned bal = __ballot_sync(0xffffffffu, lab);
            if ((tid & 31) == 0) atomicAdd(&s_cnt, __popc(bal));
        }
        __syncthreads();

        // ---- phase 3: masked sums from REGISTERS ----
        float4 lb = *(const float4*)(s_labs + 4 * j);
#pragma unroll
        for (int k = 0; k < 16; k++) {
            float a = acc1[k];
            a = fmaf(lb.x, v[k].x, a); a = fmaf(lb.y, v[k].y, a);
            a = fmaf(lb.z, v[k].z, a); a = fmaf(lb.w, v[k].w, a);
            acc1[k] = a;
        }
    }
    __syncthreads();
    if (tid == 0) accCnt += s_cnt;

    // ---- flush: half-warp reduce (16 j-lanes contiguous) + atomics ----
#pragma unroll
    for (int k = 0; k < 16; k++) {
        float a = acc1[k], s = accT[k];
#pragma unroll
        for (int o = 8; o > 0; o >>= 1) {
            a += __shfl_down_sync(0xffffffffu, a, o, 16);
            s += __shfl_down_sync(0xffffffffu, s, o, 16);
        }
        if (j == 0) {
            int c = g + 16 * k;
            atomicAdd(&g_sums[(batch * 2 + 1) * CC + c], a);
            atomicAdd(&g_sums[(batch * 2 + 0) * CC + c], s - a);
        }
    }
    if (tid == 0) {
        int npix = (t1 - t0) * TT;
        atomicAdd(&g_counts[batch * 2 + 1], (float)accCnt);
        atomicAdd(&g_counts[batch * 2 + 0], (float)(npix - accCnt));
    }

    // ---- last-finishing block performs the center update in-kernel ----
    __threadfence();
    __syncthreads();
    if (tid == 0) s_rank = atomicAdd(&g_ticket, 1u);
    __syncthreads();
    if (s_rank != (unsigned)(GRID_ASSIGN - 1)) return;
    __threadfence();  // acquire all blocks' atomics

    {
        int c = tid;
        float co0 = g_centers[c], co1 = g_centers[CC + c];
        float4 r = blockReduce4(make_float4(co0 * co0, co1 * co1, 0.f, 0.f), scr);
        float no0 = sqrtf(r.x), no1 = sqrtf(r.y);
        float nc0 = 0.f, nc1 = 0.f, cd = 0.f;
#pragma unroll
        for (int b = 0; b < BB; b++) {
            float cnt0 = g_counts[b * 2 + 0] + 1.0f;
            float cnt1 = g_counts[b * 2 + 1] + 1.0f;
            float ci0 = g_sums[(b * 2 + 0) * CC + c] / cnt0;
            float ci1 = g_sums[(b * 2 + 1) * CC + c] / cnt1;
            nc0 += ci0; nc1 += ci1;
            float4 q = blockReduce4(make_float4(ci0 * co0, ci0 * ci0, ci1 * co1, ci1 * ci1), scr);
            float den0 = fmaxf(sqrtf(q.y) * no0, 1e-8f);
            float den1 = fmaxf(sqrtf(q.w) * no1, 1e-8f);
            cd += 0.5f * (q.x / den0 + q.z / den1);
        }
        float cur = cd * 0.125f;
        nc0 *= 0.125f; nc1 *= 0.125f;
        float4 r2 = blockReduce4(make_float4(nc0 * nc0, nc1 * nc1, 0.f, 0.f), scr);
        float nn0 = fmaxf(sqrtf(r2.x), 1e-12f);
        float nn1 = fmaxf(sqrtf(r2.y), 1e-12f);
        g_centers[c] = nc0; g_centers[CC + c] = nc1;
        g_cn[c * 2 + 0] = nc0 / nn0;
        g_cn[c * 2 + 1] = nc1 / nn1;
#pragma unroll
        for (int jj = 0; jj < 16; jj++) g_sums[jj * CC + c] = 0.f;
        if (c < 16) g_counts[c] = 0.f;
        if (c == 0) {
            g_curdist = cur;
            if (cur < 0.01f) g_done = 1;
            g_ticket = 0u;   // self-reset for the next launch
        }
    }
}

// -------- finalize: write [centers | labels | onehot | cur_dist] --------
__global__ void k_final(float* __restrict__ out, long long outSize) {
    long long i = (long long)blockIdx.x * THREADS + threadIdx.x;
    if (i < 512 && i < outSize) out[i] = g_centers[i];
    if (i < (long long)BB * NN) {
        float lab = (float)g_labels[i];
        long long o1 = OFF_LABELS + i;
        long long o2 = OFF_ONEHOT + 2 * i;
        if (o1 < outSize) out[o1] = lab;
        if (o2 + 1 < outSize) {
            *(float2*)(out + o2) = make_float2(1.0f - lab, lab);
        }
    }
    if (i == 0 && OFF_CURDIST < outSize) out[OFF_CURDIST] = g_curdist;
}

extern "C" void kernel_launch(void* const* d_in, const int* in_sizes, int n_in,
                              void* d_out, int out_size) {
    const float* F = (const float*)d_in[0];
    const float* cinit = (const float*)d_in[1];
    if (n_in >= 2 && in_sizes[0] == 2 * CC) {  // tolerate swapped metadata order
        F = (const float*)d_in[1];
        cinit = (const float*)d_in[0];
    }
    k_init<<<1, THREADS>>>(cinit);
    for (int it = 0; it < 3; it++) {
        k_assign<<<GRID_ASSIGN, THREADS>>>(F);
    }
    k_final<<<(BB * NN) / THREADS, THREADS>>>((float*)d_out, (long long)out_size);
}

// round 9
// speedup vs baseline: 1.2143x; 1.1193x over previous
#include <cuda_runtime.h>

// Problem constants
#define BB 8
#define CC 256
#define NN 65536            // 256*256 spatial
#define TT 64               // pixels per tile
#define TILES_PER_BATCH 1024
#define BLOCKS_PER_BATCH 38 // batch-aligned
#define TPB 27              // ceil(1024/38)
#define GRID_ASSIGN (BB * BLOCKS_PER_BATCH)   // 304 = 2 blocks/SM * 152 SMs
#define THREADS 256

// Output layout (flat float32 concat of reference returns)
#define OFF_LABELS  512
#define OFF_ONEHOT  (512 + BB * NN)              // 524800
#define OFF_CURDIST (OFF_ONEHOT + 2LL * BB * NN) // 1573376

// -------- device scratch (no allocations allowed; zero-initialized) --------
__device__ float g_sums[BB * 2 * CC];   // [b][k][c] (re-zeroed by update tail)
__device__ float g_counts[BB * 2];      // [b][k]    (re-zeroed by update tail)
__device__ float g_centers[2 * CC];     // [k][c]
__device__ float g_cn[2 * CC];          // normalized centers, interleaved [c][k]
__device__ unsigned char g_labels[(long long)BB * NN];
__device__ float g_curdist;
__device__ int g_done;                  // reset by k_final for next replay
__device__ unsigned g_ticket;           // self-resetting

// -------- block reduce of 4 floats (256 threads) --------
__device__ __forceinline__ float4 blockReduce4(float4 v, float* scr) {
#pragma unroll
    for (int o = 16; o > 0; o >>= 1) {
        v.x += __shfl_down_sync(0xffffffffu, v.x, o);
        v.y += __shfl_down_sync(0xffffffffu, v.y, o);
        v.z += __shfl_down_sync(0xffffffffu, v.z, o);
        v.w += __shfl_down_sync(0xffffffffu, v.w, o);
    }
    int wid = threadIdx.x >> 5, lane = threadIdx.x & 31;
    __syncthreads();
    if (lane == 0) {
        scr[wid * 4 + 0] = v.x; scr[wid * 4 + 1] = v.y;
        scr[wid * 4 + 2] = v.z; scr[wid * 4 + 3] = v.w;
    }
    __syncthreads();
    if (threadIdx.x == 0) {
        float a = 0.f, b = 0.f, c = 0.f, d = 0.f;
#pragma unroll
        for (int w = 0; w < 8; w++) {
            a += scr[w * 4 + 0]; b += scr[w * 4 + 1];
            c += scr[w * 4 + 2]; d += scr[w * 4 + 3];
        }
        scr[0] = a; scr[1] = b; scr[2] = c; scr[3] = d;
    }
    __syncthreads();
    return make_float4(scr[0], scr[1], scr[2], scr[3]);
}

// -------- assign (exact R4 inner loop) + fused last-block update ----------
__global__ void __launch_bounds__(THREADS, 2) k_assign(
        const float* __restrict__ F, const float* __restrict__ cinit, int it) {
    if (it > 0 && g_done) return;  // frozen after convergence
    __shared__ float s_part[16 * 129 + 8];  // [g stride 129][8j + (q+j)&7]
    __shared__ float s_cn[2 * CC];          // interleaved [c][k]
    __shared__ float s_labs[TT];
    __shared__ float scr[32];
    __shared__ int s_cnt;
    __shared__ unsigned s_rank;

    const int tid = threadIdx.x;
    if (it == 0) {
        // per-block redundant normalization of init centers (no k_init kernel)
        float c0 = cinit[tid], c1 = cinit[CC + tid];
        float4 r = blockReduce4(make_float4(c0 * c0, c1 * c1, 0.f, 0.f), scr);
        float n0 = fmaxf(sqrtf(r.x), 1e-12f);
        float n1 = fmaxf(sqrtf(r.y), 1e-12f);
        s_cn[tid * 2 + 0] = c0 / n0;
        s_cn[tid * 2 + 1] = c1 / n1;
    } else {
        s_cn[tid] = g_cn[tid];
        s_cn[tid + 256] = g_cn[tid + 256];
    }
    if (tid == 0) s_cnt = 0;

    const int batch = blockIdx.x / BLOCKS_PER_BATCH;
    const int bi = blockIdx.x % BLOCKS_PER_BATCH;
    const int t0 = bi * TPB;
    int t1 = t0 + TPB; if (t1 > TILES_PER_BATCH) t1 = TILES_PER_BATCH;

    const int g = tid >> 4;      // channel group: channels c = g + 16k
    const int j = tid & 15;      // pixel group: pixels 4j..4j+3
    const float* Fb = F + (long long)batch * CC * NN + (long long)g * NN + 4 * j;
    const float2* cn2 = (const float2*)s_cn;

    float acc1[16], accT[16];
#pragma unroll
    for (int k = 0; k < 16; k++) { acc1[k] = 0.f; accT[k] = 0.f; }
    int accCnt = 0;
    const int poff = 129 * g + 8 * j;
    __syncthreads();  // s_cn / s_cnt ready

    for (int t = t0; t < t1; t++) {
        const float* p = Fb + t * TT;
        // ---- phase 1: streaming loads kept in registers; dots + totals ----
        float4 v[16];
        float dp[8];
#pragma unroll
        for (int q = 0; q < 8; q++) dp[q] = 0.f;
#pragma unroll
        for (int k = 0; k < 16; k++) {
            v[k] = __ldcs((const float4*)(p + (long long)k * (16 * NN)));
            float2 w = cn2[g + 16 * k];
            dp[0] = fmaf(v[k].x, w.x, dp[0]); dp[1] = fmaf(v[k].x, w.y, dp[1]);
            dp[2] = fmaf(v[k].y, w.x, dp[2]); dp[3] = fmaf(v[k].y, w.y, dp[3]);
            dp[4] = fmaf(v[k].z, w.x, dp[4]); dp[5] = fmaf(v[k].z, w.y, dp[5]);
            dp[6] = fmaf(v[k].w, w.x, dp[6]); dp[7] = fmaf(v[k].w, w.y, dp[7]);
            accT[k] += (v[k].x + v[k].y) + (v[k].z + v[k].w);
        }
        // harvest previous tile's count (ballots completed before last barrier)
        if (tid == 0) { accCnt += s_cnt; s_cnt = 0; }
        // swizzled partial store: conflict-free writes & reads
#pragma unroll
        for (int q = 0; q < 8; q++)
            s_part[poff + ((q + j) & 7)] = dp[q];
        __syncthreads();

        // ---- phase 2: reduce 16 groups -> dots, labels ----
        if (tid < 128) {
            const int off = 8 * (tid >> 3) + (((tid & 7) + (tid >> 3)) & 7);
            float s = 0.f;
#pragma unroll
            for (int gg = 0; gg < 16; gg++) s += s_part[129 * gg + off];
            float o = __shfl_xor_sync(0xffffffffu, s, 1);
            int lab = 0;
            if (!(tid & 1)) {
                lab = (o > s) ? 1 : 0;  // argmin tie -> 0
                int pidx = tid >> 1;
                s_labs[pidx] = (float)lab;
                g_labels[(long long)batch * NN + t * TT + pidx] = (unsigned char)lab;
            }
            unsigned bal = __ballot_sync(0xffffffffu, lab);
            if ((tid & 31) == 0) atomicAdd(&s_cnt, __popc(bal));
        }
        __syncthreads();

        // ---- phase 3: masked sums from REGISTERS ----
        float4 lb = *(const float4*)(s_labs + 4 * j);
#pragma unroll
        for (int k = 0; k < 16; k++) {
            float a = acc1[k];
            a = fmaf(lb.x, v[k].x, a); a = fmaf(lb.y, v[k].y, a);
            a = fmaf(lb.z, v[k].z, a); a = fmaf(lb.w, v[k].w, a);
            acc1[k] = a;
        }
    }
    __syncthreads();
    if (tid == 0) accCnt += s_cnt;

    // ---- flush: half-warp reduce (16 j-lanes contiguous) + atomics ----
#pragma unroll
    for (int k = 0; k < 16; k++) {
        float a = acc1[k], s = accT[k];
#pragma unroll
        for (int o = 8; o > 0; o >>= 1) {
            a += __shfl_down_sync(0xffffffffu, a, o, 16);
            s += __shfl_down_sync(0xffffffffu, s, o, 16);
        }
        if (j == 0) {
            int c = g + 16 * k;
            atomicAdd(&g_sums[(batch * 2 + 1) * CC + c], a);
            atomicAdd(&g_sums[(batch * 2 + 0) * CC + c], s - a);
        }
    }
    if (tid == 0) {
        int npix = (t1 - t0) * TT;
        atomicAdd(&g_counts[batch * 2 + 1], (float)accCnt);
        atomicAdd(&g_counts[batch * 2 + 0], (float)(npix - accCnt));
    }

    // ---- last-finishing block performs the center update in-kernel ----
    __threadfence();
    __syncthreads();
    if (tid == 0) s_rank = atomicAdd(&g_ticket, 1u);
    __syncthreads();
    if (s_rank != (unsigned)(GRID_ASSIGN - 1)) return;
    __threadfence();  // acquire all blocks' atomics

    {
        int c = tid;
        float co0, co1;
        if (it == 0) { co0 = cinit[c]; co1 = cinit[CC + c]; }
        else         { co0 = g_centers[c]; co1 = g_centers[CC + c]; }
        float4 r = blockReduce4(make_float4(co0 * co0, co1 * co1, 0.f, 0.f), scr);
        float no0 = sqrtf(r.x), no1 = sqrtf(r.y);
        float nc0 = 0.f, nc1 = 0.f, cd = 0.f;
#pragma unroll
        for (int b = 0; b < BB; b++) {
            float cnt0 = g_counts[b * 2 + 0] + 1.0f;
            float cnt1 = g_counts[b * 2 + 1] + 1.0f;
            float ci0 = g_sums[(b * 2 + 0) * CC + c] / cnt0;
            float ci1 = g_sums[(b * 2 + 1) * CC + c] / cnt1;
            nc0 += ci0; nc1 += ci1;
            float4 q = blockReduce4(make_float4(ci0 * co0, ci0 * ci0, ci1 * co1, ci1 * ci1), scr);
            float den0 = fmaxf(sqrtf(q.y) * no0, 1e-8f);
            float den1 = fmaxf(sqrtf(q.w) * no1, 1e-8f);
            cd += 0.5f * (q.x / den0 + q.z / den1);
        }
        float cur = cd * 0.125f;
        nc0 *= 0.125f; nc1 *= 0.125f;
        float4 r2 = blockReduce4(make_float4(nc0 * nc0, nc1 * nc1, 0.f, 0.f), scr);
        float nn0 = fmaxf(sqrtf(r2.x), 1e-12f);
        float nn1 = fmaxf(sqrtf(r2.y), 1e-12f);
        g_centers[c] = nc0; g_centers[CC + c] = nc1;
        g_cn[c * 2 + 0] = nc0 / nn0;
        g_cn[c * 2 + 1] = nc1 / nn1;
#pragma unroll
        for (int jj = 0; jj < 16; jj++) g_sums[jj * CC + c] = 0.f;  // re-zero
        if (c < 16) g_counts[c] = 0.f;
        if (c == 0) {
            g_curdist = cur;
            if (cur < 0.01f) g_done = 1;
            g_ticket = 0u;   // self-reset for the next launch
        }
    }
}

// -------- finalize: write [centers | labels | onehot | cur_dist] --------
__global__ void k_final(float* __restrict__ out, long long outSize) {
    long long i = (long long)blockIdx.x * THREADS + threadIdx.x;
    if (i < 512 && i < outSize) out[i] = g_centers[i];
    if (i < (long long)BB * NN) {
        float lab = (float)g_labels[i];
        long long o1 = OFF_LABELS + i;
        long long o2 = OFF_ONEHOT + 2 * i;
        if (o1 < outSize) out[o1] = lab;
        if (o2 + 1 < outSize) {
            *(float2*)(out + o2) = make_float2(1.0f - lab, lab);
        }
    }
    if (i == 0) {
        if (OFF_CURDIST < outSize) out[OFF_CURDIST] = g_curdist;
        g_done = 0;   // reset for next graph replay (determinism)
    }
}

extern "C" void kernel_launch(void* const* d_in, const int* in_sizes, int n_in,
                              void* d_out, int out_size) {
    const float* F = (const float*)d_in[0];
    const float* cinit = (const float*)d_in[1];
    if (n_in >= 2 && in_sizes[0] == 2 * CC) {  // tolerate swapped metadata order
        F = (const float*)d_in[1];
        cinit = (const float*)d_in[0];
    }
    for (int it = 0; it < 3; it++) {
        k_assign<<<GRID_ASSIGN, THREADS>>>(F, cinit, it);
    }
    k_final<<<(BB * NN) / THREADS, THREADS>>>((float*)d_out, (long long)out_size);
}